// round 14
// baseline (speedup 1.0000x reference)
#include <cuda_runtime.h>
#include <cstdint>

#define Lq    4096
#define DIN   512
#define DOUTC 256
#define NH    4
#define HD    64
#define CJ    32
#define JC    32                 // chunks per CTA (quarter of K range)
#define JQ    1024               // j extent per CTA
#define NSPLIT 4

typedef unsigned long long ull;

// ---------------- scratch (device globals; no allocs allowed) ----------------
__device__ float    g_Wh[Lq * DOUTC];
__device__ float    g_WhT[DOUTC * Lq];        // [c][l], k-paired within 8-blocks
__device__ float    g_patt[NSPLIT * Lq * DOUTC];
__device__ float    g_den[NSPLIT * NH * Lq];
__device__ float    g_dinv[NH * Lq];
__device__ float    g_e1i[NH * Lq];
__device__ float    g_e2i[NH * Lq];
__device__ float    g_ejp[NH * Lq * 2];       // paired (e1,e2,e1+4,e2+4) per (blk,q)
__device__ uint32_t g_maskT[(Lq / 32) * Lq];

__device__ __forceinline__ uint32_t tf32r(float x) {
    uint32_t u;
    asm("cvt.rna.tf32.f32 %0, %1;" : "=r"(u) : "f"(x));
    return u;
}
__device__ __forceinline__ uint32_t s2u(const void* p) {
    uint32_t a;
    asm("{ .reg .u64 t; cvta.to.shared.u64 t, %1; cvt.u32.u64 %0, t; }"
        : "=r"(a) : "l"(p));
    return a;
}
__device__ __forceinline__ void cpa16(uint32_t dst, const void* src) {
    asm volatile("cp.async.cg.shared.global [%0], [%1], 16;"
                 :: "r"(dst), "l"(src));
}
#define CPA_COMMIT() asm volatile("cp.async.commit_group;")
#define CPA_WAIT0()  asm volatile("cp.async.wait_group 0;")

__device__ __forceinline__ ull pack2(float x, float y) {
    ull r;
    asm("mov.b64 %0, {%1, %2};" : "=l"(r) : "f"(x), "f"(y));
    return r;
}
__device__ __forceinline__ void fma2(ull& d, ull a, ull b) {
    asm("fma.rn.f32x2 %0, %1, %2, %0;" : "+l"(d) : "l"(a), "l"(b));
}
__device__ __forceinline__ float2 unpack2(ull v) {
    float2 f;
    asm("mov.b64 {%0, %1}, %2;" : "=f"(f.x), "=f"(f.y) : "l"(v));
    return f;
}
__device__ __forceinline__ void mma_tf32(float* c, uint32_t a0, uint32_t a1,
                                         uint32_t a2, uint32_t a3,
                                         uint32_t b0, uint32_t b1) {
    asm volatile(
        "mma.sync.aligned.m16n8k8.row.col.f32.tf32.tf32.f32 "
        "{%0,%1,%2,%3}, {%4,%5,%6,%7}, {%8,%9}, {%0,%1,%2,%3};"
        : "+f"(c[0]), "+f"(c[1]), "+f"(c[2]), "+f"(c[3])
        : "r"(a0), "r"(a1), "r"(a2), "r"(a3), "r"(b0), "r"(b1));
}

// ---------------- pipelined f32x2 GEMM: C = A @ B^T (+bias) ------------------
template <int K, int MODE>
__global__ void __launch_bounds__(256) gemm64_nt(const float* __restrict__ Aext,
                                                 const float* __restrict__ Bm,
                                                 float* __restrict__ Cext,
                                                 const float* __restrict__ bias) {
    __shared__ float As[16][68];
    __shared__ float Bs[16][68];

    int tid = threadIdx.x;
    int m0 = blockIdx.y * 64, n0 = blockIdx.x * 64;
    int tx = tid & 15, ty = tid >> 4;
    int r  = tid >> 2;
    int kk = (tid & 3) * 4;

    float4 av, bv;
    {
        if (MODE == 0) {
            av = *(const float4*)&Aext[(size_t)(m0 + r) * K + kk];
        } else {
            float4 p = *(const float4*)&g_patt[(size_t)(m0 + r) * K + kk];
#pragma unroll
            for (int s = 1; s < NSPLIT; s++) {
                float4 q = *(const float4*)&g_patt[(size_t)s * Lq * DOUTC +
                                                   (size_t)(m0 + r) * K + kk];
                p.x += q.x; p.y += q.y; p.z += q.z; p.w += q.w;
            }
            float inv = __ldg(&g_dinv[(kk >> 6) * Lq + m0 + r]);
            av = make_float4(p.x * inv, p.y * inv, p.z * inv, p.w * inv);
        }
        bv = *(const float4*)&Bm[(size_t)(n0 + r) * K + kk];
    }

    ull acc2[2][4];
#pragma unroll
    for (int p = 0; p < 2; p++)
#pragma unroll
        for (int j = 0; j < 4; j++) acc2[p][j] = 0ull;

    const int NCK = K / 16;
    for (int c = 0; c < NCK; c++) {
        As[kk + 0][r] = av.x; As[kk + 1][r] = av.y;
        As[kk + 2][r] = av.z; As[kk + 3][r] = av.w;
        Bs[kk + 0][r] = bv.x; Bs[kk + 1][r] = bv.y;
        Bs[kk + 2][r] = bv.z; Bs[kk + 3][r] = bv.w;
        __syncthreads();

        if (c + 1 < NCK) {
            int k0 = (c + 1) * 16;
            if (MODE == 0) {
                av = *(const float4*)&Aext[(size_t)(m0 + r) * K + k0 + kk];
            } else {
                float4 p = *(const float4*)&g_patt[(size_t)(m0 + r) * K + k0 + kk];
#pragma unroll
                for (int s = 1; s < NSPLIT; s++) {
                    float4 q = *(const float4*)&g_patt[(size_t)s * Lq * DOUTC +
                                                       (size_t)(m0 + r) * K + k0 + kk];
                    p.x += q.x; p.y += q.y; p.z += q.z; p.w += q.w;
                }
                float inv = __ldg(&g_dinv[((k0 + kk) >> 6) * Lq + m0 + r]);
                av = make_float4(p.x * inv, p.y * inv, p.z * inv, p.w * inv);
            }
            bv = *(const float4*)&Bm[(size_t)(n0 + r) * K + k0 + kk];
        }

#pragma unroll
        for (int k = 0; k < 16; k++) {
            ulonglong2 aa = *(const ulonglong2*)&As[k][ty * 4];
            float4 b = *(const float4*)&Bs[k][tx * 4];
            ull bx = pack2(b.x, b.x), by = pack2(b.y, b.y);
            ull bz = pack2(b.z, b.z), bw = pack2(b.w, b.w);
            fma2(acc2[0][0], aa.x, bx); fma2(acc2[0][1], aa.x, by);
            fma2(acc2[0][2], aa.x, bz); fma2(acc2[0][3], aa.x, bw);
            fma2(acc2[1][0], aa.y, bx); fma2(acc2[1][1], aa.y, by);
            fma2(acc2[1][2], aa.y, bz); fma2(acc2[1][3], aa.y, bw);
        }
        __syncthreads();
    }

    float acc[4][4];
#pragma unroll
    for (int p = 0; p < 2; p++)
#pragma unroll
        for (int j = 0; j < 4; j++) {
            float2 v = unpack2(acc2[p][j]);
            acc[2 * p][j] = v.x;
            acc[2 * p + 1][j] = v.y;
        }

    float4 bvb = make_float4(0.f, 0.f, 0.f, 0.f);
    if (MODE == 1) bvb = *(const float4*)&bias[n0 + tx * 4];
    float* Cm = (MODE == 0) ? g_Wh : Cext;
#pragma unroll
    for (int i = 0; i < 4; i++) {
        float4 o = make_float4(acc[i][0] + bvb.x, acc[i][1] + bvb.y,
                               acc[i][2] + bvb.z, acc[i][3] + bvb.w);
        *(float4*)&Cm[(size_t)(m0 + ty * 4 + i) * DOUTC + n0 + tx * 4] = o;
    }
    if (MODE == 0) {
        // k-paired tf32 store: within each 8-block of l, order (0,4,1,5,2,6,3,7)
#pragma unroll
        for (int j = 0; j < 4; j++) {
#pragma unroll
            for (int i = 0; i < 4; i++) {
                int l = m0 + ty * 4 + i;
                int p = 2 * (l & 3) + ((l >> 2) & 1);
                g_WhT[(size_t)(n0 + tx * 4 + j) * Lq + (l & ~7) + p] =
                    __uint_as_float(tf32r(acc[i][j]));
            }
        }
    }
}

// ---------------- s kernel: row factors + paired j tables --------------------
__global__ void __launch_bounds__(256) s_kernel(const float* __restrict__ attn) {
    int gw = blockIdx.x * 8 + (threadIdx.x >> 5);
    int lane = threadIdx.x & 31;
    int l = gw >> 2, hh = gw & 3;
    const float* whp = &g_Wh[(size_t)l * DOUTC + hh * HD];
    float v0 = whp[lane], v1 = whp[lane + 32];
    const float* ap = &attn[hh * 2 * HD];
    float si = v0 * ap[lane]      + v1 * ap[lane + 32];
    float sj = v0 * ap[64 + lane] + v1 * ap[96 + lane];
#pragma unroll
    for (int o = 16; o; o >>= 1) {
        si += __shfl_xor_sync(0xffffffffu, si, o);
        sj += __shfl_xor_sync(0xffffffffu, sj, o);
    }
    if (lane == 0) {
        g_e1i[hh * Lq + l] = __expf(si);
        g_e2i[hh * Lq + l] = __expf(0.2f * si);
        int block = l >> 3, t8 = l & 7;
        int q = t8 & 3, hi = t8 >> 2;
        float* dst = &g_ejp[(size_t)(((hh * (Lq / 8) + block) * 4 + q) * 4) + hi * 2];
        dst[0] = __expf(sj);
        dst[1] = __expf(0.2f * sj);
    }
}

// ---------------- mask kernel ------------------------------------------------
__global__ void __launch_bounds__(256) mask_kernel(const int* __restrict__ A) {
    int lane = threadIdx.x & 31, wid = threadIdx.x >> 5;
    int row = blockIdx.x * 8 + wid;
    const int* Arow = A + (size_t)row * Lq;
    for (int w = 0; w < Lq / 32; w++) {
        uint32_t b = __ballot_sync(0xffffffffu, Arow[w * 32 + lane] > 0);
        if (lane == 0) g_maskT[(size_t)w * Lq + row] = b;
    }
}

// ---------------- dinv: 1/sum(d) ----------------------------------------------
__global__ void __launch_bounds__(256) dinv_kernel() {
    int idx = blockIdx.x * 256 + threadIdx.x;
    float d = 0.f;
#pragma unroll
    for (int s = 0; s < NSPLIT; s++) d += g_den[s * NH * Lq + idx];
    g_dinv[idx] = (d > 0.f) ? 1.f / d : 0.f;
}

// ---------------- mma.sync attention: 128 thr, warp = 32 rows, quarter-j -----
// smem (~44 KB -> 3 CTAs/SM):
//   b_s   : 2 x [64][40] f32   20480 B
//   ejp_s : [JQ/8][4] f4        8192 B
//   mask_s: [32][128] u32      16384 B
#define BPAD   40
#define BBUF   (64 * BPAD)
#define SM_B    0
#define SM_EJP  (2 * BBUF * 4)             // 20480
#define SM_MASK (SM_EJP + JQ * 2 * 4)      // 28672
#define SM_TOT  (SM_MASK + JC * 128 * 4)   // 45056

__global__ void __launch_bounds__(128, 3) gat_attn_mma() {
    extern __shared__ char smem[];
    uint32_t smb = s2u(smem);
    float*        b_s    = (float*)(smem + SM_B);
    const float4* ejp_s  = (const float4*)(smem + SM_EJP);
    uint32_t*     mask_s = (uint32_t*)(smem + SM_MASK);

    int tid = threadIdx.x, lane = tid & 31, wid = tid >> 5;
    int tile = blockIdx.x & 31;
    int h    = (blockIdx.x >> 5) & 3;
    int jq   = blockIdx.x >> 7;          // 0..3
    int i0   = tile * 128;
    int jb   = jq * JQ;

    int q4 = lane & 3;
    int rg = lane >> 2;
    int rbase = wid * 32 + rg;           // warp owns rows rbase + {0,8,16,24}

    float E1[4], E2[4];
#pragma unroll
    for (int rr = 0; rr < 4; rr++) {
        E1[rr] = __ldg(&g_e1i[h * Lq + i0 + rbase + rr * 8]);
        E2[rr] = __ldg(&g_e2i[h * Lq + i0 + rbase + rr * 8]);
    }

#define PREF_B(c, nb) do {                                                     \
        _Pragma("unroll")                                                      \
        for (int q = 0; q < 4; q++) {                                          \
            int idx = tid + q * 128;                                           \
            int n = idx >> 3, k4 = idx & 7;                                    \
            cpa16(smb + SM_B + (nb) * BBUF * 4 + n * (BPAD * 4) + k4 * 16,     \
                  &g_WhT[(size_t)(h * HD + n) * Lq + jb + (c) * CJ + k4 * 4]); \
        }                                                                      \
        CPA_COMMIT();                                                          \
    } while (0)

    PREF_B(0, 0);
#pragma unroll
    for (int q = 0; q < 8; q++) {        // 32 words x 128 rows = 1024 x 16B
        int idx = tid + q * 128;
        int w = idx >> 5, r4 = idx & 31;
        cpa16(smb + SM_MASK + idx * 16,
              &g_maskT[(size_t)(jq * JC + w) * Lq + i0 + r4 * 4]);
    }
#pragma unroll
    for (int q = 0; q < 4; q++) {        // ejp quarter: 2048 floats = 512 x 16B
        int idx = tid + q * 128;
        cpa16(smb + SM_EJP + idx * 16,
              &g_ejp[(size_t)(h * (Lq / 8) + jb / 8) * 16 + idx * 4]);
    }
    CPA_COMMIT();
    CPA_WAIT0();
    __syncthreads();

    float c_acc[2][8][4];
#pragma unroll
    for (int tt = 0; tt < 2; tt++)
#pragma unroll
        for (int t = 0; t < 8; t++)
#pragma unroll
            for (int p = 0; p < 4; p++) c_acc[tt][t][p] = 0.f;
    float dsum[4] = {0.f, 0.f, 0.f, 0.f};

    for (int c = 0; c < JC; c++) {
        int cur = c & 1;
        if (c + 1 < JC) PREF_B(c + 1, cur ^ 1);

        uint32_t mw[4];
#pragma unroll
        for (int rr = 0; rr < 4; rr++)
            mw[rr] = mask_s[c * 128 + rbase + rr * 8] >> q4;
        const float* bb = b_s + cur * BBUF + rg * BPAD;

#pragma unroll
        for (int ks = 0; ks < 4; ks++) {
            float4 ee = ejp_s[(c * 4 + ks) * 4 + q4];   // e1a,e2a,e1b,e2b
            float ma[4], mb[4];
#pragma unroll
            for (int rr = 0; rr < 4; rr++) {
                float v1 = fmaxf(E1[rr] * ee.x, E2[rr] * ee.y);
                float v2 = fmaxf(E1[rr] * ee.z, E2[rr] * ee.w);
                ma[rr] = (mw[rr] & (1u << (ks * 8)))     ? v1 : 0.f;
                mb[rr] = (mw[rr] & (1u << (ks * 8 + 4))) ? v2 : 0.f;
                dsum[rr] += ma[rr] + mb[rr];
            }
            uint32_t a00 = __float_as_uint(ma[0]), a01 = __float_as_uint(ma[1]);
            uint32_t a02 = __float_as_uint(mb[0]), a03 = __float_as_uint(mb[1]);
            uint32_t a10 = __float_as_uint(ma[2]), a11 = __float_as_uint(ma[3]);
            uint32_t a12 = __float_as_uint(mb[2]), a13 = __float_as_uint(mb[3]);
#pragma unroll
            for (int t = 0; t < 8; t++) {
                uint2 b01 = *(const uint2*)&bb[t * 8 * BPAD + ks * 8 + q4 * 2];
                mma_tf32(c_acc[0][t], a00, a01, a02, a03, b01.x, b01.y);
                mma_tf32(c_acc[1][t], a10, a11, a12, a13, b01.x, b01.y);
            }
        }

        if (c + 1 < JC) CPA_WAIT0();
        __syncthreads();
    }

    // denominators: reduce over the 4 lanes sharing a row
#pragma unroll
    for (int rr = 0; rr < 4; rr++) {
#pragma unroll
        for (int o = 1; o <= 2; o <<= 1)
            dsum[rr] += __shfl_xor_sync(0xffffffffu, dsum[rr], o);
    }
    if (q4 == 0) {
#pragma unroll
        for (int rr = 0; rr < 4; rr++)
            g_den[(size_t)jq * NH * Lq + h * Lq + i0 + rbase + rr * 8] = dsum[rr];
    }

    // partial writeback
    int col0 = h * HD + q4 * 2;
#pragma unroll
    for (int tt = 0; tt < 2; tt++) {
        int row1 = i0 + rbase + tt * 16;
        int row2 = row1 + 8;
        float* d1 = g_patt + (size_t)jq * Lq * DOUTC + (size_t)row1 * DOUTC + col0;
        float* d2 = g_patt + (size_t)jq * Lq * DOUTC + (size_t)row2 * DOUTC + col0;
#pragma unroll
        for (int t = 0; t < 8; t++) {
            *(float2*)(d1 + t * 8) = make_float2(c_acc[tt][t][0], c_acc[tt][t][1]);
            *(float2*)(d2 + t * 8) = make_float2(c_acc[tt][t][2], c_acc[tt][t][3]);
        }
    }
}

// ---------------- launch ------------------------------------------------------
extern "C" void kernel_launch(void* const* d_in, const int* in_sizes, int n_in,
                              void* d_out, int out_size) {
    const float* h     = (const float*)d_in[0];
    const int*   A     = (const int*)d_in[1];
    const float* W     = (const float*)d_in[2];
    const float* attn  = (const float*)d_in[3];
    const float* out_w = (const float*)d_in[4];
    const float* out_b = (const float*)d_in[5];
    float*       out   = (float*)d_out;

    gemm64_nt<DIN, 0><<<dim3(DOUTC / 64, Lq / 64), 256>>>(h, W, nullptr, nullptr);
    mask_kernel<<<Lq / 8, 256>>>(A);
    s_kernel<<<(Lq * NH) / 8, 256>>>(attn);
    cudaFuncSetAttribute(gat_attn_mma,
                         cudaFuncAttributeMaxDynamicSharedMemorySize, SM_TOT);
    gat_attn_mma<<<(Lq / 128) * NH * NSPLIT, 128, SM_TOT>>>();
    dinv_kernel<<<(NH * Lq) / 256, 256>>>();
    gemm64_nt<DOUTC, 1><<<dim3(DOUTC / 64, Lq / 64), 256>>>(nullptr, out_w, out, out_b);
}

// round 15
// speedup vs baseline: 1.0870x; 1.0870x over previous
#include <cuda_runtime.h>
#include <cstdint>

#define Lq    4096
#define DIN   512
#define DOUTC 256
#define NH    4
#define HD    64
#define CJ    32
#define JC    64
#define JHALF 2048

typedef unsigned long long ull;

// ---------------- scratch (device globals; no allocs allowed) ----------------
__device__ float    g_WhT[DOUTC * Lq];        // [c][l], k-paired within 8-blocks
__device__ float    g_patt[2 * Lq * DOUTC];
__device__ float    g_den[2 * NH * Lq];
__device__ float    g_dinv[NH * Lq];
__device__ float    g_e1i[NH * Lq];
__device__ float    g_e2i[NH * Lq];
__device__ float    g_ejp[NH * Lq * 2];       // paired (e1,e2,e1+4,e2+4) per (blk,q)
__device__ uint32_t g_maskT[(Lq / 32) * Lq];  // [word][row]

__device__ __forceinline__ uint32_t tf32r(float x) {
    uint32_t u;
    asm("cvt.rna.tf32.f32 %0, %1;" : "=r"(u) : "f"(x));
    return u;
}
__device__ __forceinline__ uint32_t s2u(const void* p) {
    uint32_t a;
    asm("{ .reg .u64 t; cvta.to.shared.u64 t, %1; cvt.u32.u64 %0, t; }"
        : "=r"(a) : "l"(p));
    return a;
}
__device__ __forceinline__ void cpa16(uint32_t dst, const void* src) {
    asm volatile("cp.async.cg.shared.global [%0], [%1], 16;"
                 :: "r"(dst), "l"(src));
}
#define CPA_COMMIT() asm volatile("cp.async.commit_group;")
#define CPA_WAIT0()  asm volatile("cp.async.wait_group 0;")

__device__ __forceinline__ ull pack2(float x, float y) {
    ull r;
    asm("mov.b64 %0, {%1, %2};" : "=l"(r) : "f"(x), "f"(y));
    return r;
}
__device__ __forceinline__ void fma2(ull& d, ull a, ull b) {
    asm("fma.rn.f32x2 %0, %1, %2, %0;" : "+l"(d) : "l"(a), "l"(b));
}
__device__ __forceinline__ float2 unpack2(ull v) {
    float2 f;
    asm("mov.b64 {%0, %1}, %2;" : "=f"(f.x), "=f"(f.y) : "l"(v));
    return f;
}
__device__ __forceinline__ void mma_tf32(float* c, uint32_t a0, uint32_t a1,
                                         uint32_t a2, uint32_t a3,
                                         uint32_t b0, uint32_t b1) {
    asm volatile(
        "mma.sync.aligned.m16n8k8.row.col.f32.tf32.tf32.f32 "
        "{%0,%1,%2,%3}, {%4,%5,%6,%7}, {%8,%9}, {%0,%1,%2,%3};"
        : "+f"(c[0]), "+f"(c[1]), "+f"(c[2]), "+f"(c[3])
        : "r"(a0), "r"(a1), "r"(a2), "r"(a3), "r"(b0), "r"(b1));
}

// ---------------- pipelined f32x2 GEMM: C = A @ B^T (+bias) ------------------
// MODE 0: A = h, K = DIN. Output: g_WhT (tf32, k-paired) + fused s-tables
//         (si/sj dot with a1/a2, where `bias` carries the attn vector).
// MODE 1: A = (patt0+patt1)*dinv, K = DOUTC. Output: Cext + bias.
template <int K, int MODE>
__global__ void __launch_bounds__(256) gemm64_nt(const float* __restrict__ Aext,
                                                 const float* __restrict__ Bm,
                                                 float* __restrict__ Cext,
                                                 const float* __restrict__ bias) {
    __shared__ float As[16][68];
    __shared__ float Bs[16][68];

    int tid = threadIdx.x;
    int m0 = blockIdx.y * 64, n0 = blockIdx.x * 64;
    int tx = tid & 15, ty = tid >> 4;
    int r  = tid >> 2;
    int kk = (tid & 3) * 4;

    float4 av, bv;
    {
        if (MODE == 0) {
            av = *(const float4*)&Aext[(size_t)(m0 + r) * K + kk];
        } else {
            float4 p0 = *(const float4*)&g_patt[(size_t)(m0 + r) * K + kk];
            float4 p1 = *(const float4*)&g_patt[(size_t)Lq * DOUTC +
                                                (size_t)(m0 + r) * K + kk];
            float inv = __ldg(&g_dinv[(kk >> 6) * Lq + m0 + r]);
            av = make_float4((p0.x + p1.x) * inv, (p0.y + p1.y) * inv,
                             (p0.z + p1.z) * inv, (p0.w + p1.w) * inv);
        }
        bv = *(const float4*)&Bm[(size_t)(n0 + r) * K + kk];
    }

    ull acc2[2][4];
#pragma unroll
    for (int p = 0; p < 2; p++)
#pragma unroll
        for (int j = 0; j < 4; j++) acc2[p][j] = 0ull;

    const int NCK = K / 16;
    for (int c = 0; c < NCK; c++) {
        As[kk + 0][r] = av.x; As[kk + 1][r] = av.y;
        As[kk + 2][r] = av.z; As[kk + 3][r] = av.w;
        Bs[kk + 0][r] = bv.x; Bs[kk + 1][r] = bv.y;
        Bs[kk + 2][r] = bv.z; Bs[kk + 3][r] = bv.w;
        __syncthreads();

        if (c + 1 < NCK) {
            int k0 = (c + 1) * 16;
            if (MODE == 0) {
                av = *(const float4*)&Aext[(size_t)(m0 + r) * K + k0 + kk];
            } else {
                float4 p0 = *(const float4*)&g_patt[(size_t)(m0 + r) * K + k0 + kk];
                float4 p1 = *(const float4*)&g_patt[(size_t)Lq * DOUTC +
                                                    (size_t)(m0 + r) * K + k0 + kk];
                float inv = __ldg(&g_dinv[((k0 + kk) >> 6) * Lq + m0 + r]);
                av = make_float4((p0.x + p1.x) * inv, (p0.y + p1.y) * inv,
                                 (p0.z + p1.z) * inv, (p0.w + p1.w) * inv);
            }
            bv = *(const float4*)&Bm[(size_t)(n0 + r) * K + k0 + kk];
        }

#pragma unroll
        for (int k = 0; k < 16; k++) {
            ulonglong2 aa = *(const ulonglong2*)&As[k][ty * 4];
            float4 b = *(const float4*)&Bs[k][tx * 4];
            ull bx = pack2(b.x, b.x), by = pack2(b.y, b.y);
            ull bz = pack2(b.z, b.z), bw = pack2(b.w, b.w);
            fma2(acc2[0][0], aa.x, bx); fma2(acc2[0][1], aa.x, by);
            fma2(acc2[0][2], aa.x, bz); fma2(acc2[0][3], aa.x, bw);
            fma2(acc2[1][0], aa.y, bx); fma2(acc2[1][1], aa.y, by);
            fma2(acc2[1][2], aa.y, bz); fma2(acc2[1][3], aa.y, bw);
        }
        __syncthreads();
    }

    float acc[4][4];
#pragma unroll
    for (int p = 0; p < 2; p++)
#pragma unroll
        for (int j = 0; j < 4; j++) {
            float2 v = unpack2(acc2[p][j]);
            acc[2 * p][j] = v.x;
            acc[2 * p + 1][j] = v.y;
        }

    if (MODE == 1) {
        float4 bvb = *(const float4*)&bias[n0 + tx * 4];
#pragma unroll
        for (int i = 0; i < 4; i++) {
            float4 o = make_float4(acc[i][0] + bvb.x, acc[i][1] + bvb.y,
                                   acc[i][2] + bvb.z, acc[i][3] + bvb.w);
            *(float4*)&Cext[(size_t)(m0 + ty * 4 + i) * DOUTC + n0 + tx * 4] = o;
        }
    }

    if (MODE == 0) {
        // k-paired tf32 store: within each 8-block of l, order (0,4,1,5,2,6,3,7)
#pragma unroll
        for (int j = 0; j < 4; j++) {
#pragma unroll
            for (int i = 0; i < 4; i++) {
                int l = m0 + ty * 4 + i;
                int p = 2 * (l & 3) + ((l >> 2) & 1);
                g_WhT[(size_t)(n0 + tx * 4 + j) * Lq + (l & ~7) + p] =
                    __uint_as_float(tf32r(acc[i][j]));
            }
        }

        // fused s-tables: this CTA's head is hh = n0/64; bias = attn vector
        int hh = n0 >> 6;
        const float4 a1v = *(const float4*)&bias[hh * 2 * HD + tx * 4];
        const float4 a2v = *(const float4*)&bias[hh * 2 * HD + HD + tx * 4];
        float psi[4], psj[4];
#pragma unroll
        for (int i = 0; i < 4; i++) {
            psi[i] = acc[i][0] * a1v.x + acc[i][1] * a1v.y +
                     acc[i][2] * a1v.z + acc[i][3] * a1v.w;
            psj[i] = acc[i][0] * a2v.x + acc[i][1] * a2v.y +
                     acc[i][2] * a2v.z + acc[i][3] * a2v.w;
        }
#pragma unroll
        for (int o = 1; o <= 8; o <<= 1) {
#pragma unroll
            for (int i = 0; i < 4; i++) {
                psi[i] += __shfl_xor_sync(0xffffffffu, psi[i], o);
                psj[i] += __shfl_xor_sync(0xffffffffu, psj[i], o);
            }
        }
        if (tx == 0) {
#pragma unroll
            for (int i = 0; i < 4; i++) {
                int l = m0 + ty * 4 + i;
                g_e1i[hh * Lq + l] = __expf(psi[i]);
                g_e2i[hh * Lq + l] = __expf(0.2f * psi[i]);
                int block = l >> 3, t8 = l & 7;
                int q = t8 & 3, hi = t8 >> 2;
                float* dst =
                    &g_ejp[(size_t)(((hh * (Lq / 8) + block) * 4 + q) * 4) + hi * 2];
                dst[0] = __expf(psj[i]);
                dst[1] = __expf(0.2f * psj[i]);
            }
        }
    }
}

// ---------------- mask kernel ------------------------------------------------
__global__ void __launch_bounds__(256) mask_kernel(const int* __restrict__ A) {
    int lane = threadIdx.x & 31, wid = threadIdx.x >> 5;
    int row = blockIdx.x * 8 + wid;
    const int* Arow = A + (size_t)row * Lq;
    for (int w = 0; w < Lq / 32; w++) {
        uint32_t b = __ballot_sync(0xffffffffu, Arow[w * 32 + lane] > 0);
        if (lane == 0) g_maskT[(size_t)w * Lq + row] = b;
    }
}

// ---------------- dinv: 1/(d0+d1) --------------------------------------------
__global__ void __launch_bounds__(256) dinv_kernel() {
    int idx = blockIdx.x * 256 + threadIdx.x;
    float d = g_den[idx] + g_den[NH * Lq + idx];
    g_dinv[idx] = (d > 0.f) ? 1.f / d : 0.f;
}

// ---------------- mma.sync attention: 128 threads, warp = 32 rows ------------
// smem (~68 KB):
//   b_s   : 2 x [64][40] f32   20480 B (k-paired, BPAD=40)
//   ejp_s : [JHALF/8][4] f4    16384 B
//   mask_s: [64][128] u32      32768 B
#define BPAD   40
#define BBUF   (64 * BPAD)
#define SM_B    0
#define SM_EJP  (2 * BBUF * 4)
#define SM_MASK (SM_EJP + JHALF * 2 * 4)
#define SM_TOT  (SM_MASK + JC * 128 * 4)

__global__ void __launch_bounds__(128, 3) gat_attn_mma() {
    extern __shared__ char smem[];
    uint32_t smb = s2u(smem);
    float*        b_s    = (float*)(smem + SM_B);
    const float4* ejp_s  = (const float4*)(smem + SM_EJP);
    uint32_t*     mask_s = (uint32_t*)(smem + SM_MASK);

    int tid = threadIdx.x, lane = tid & 31, wid = tid >> 5;
    int tile = blockIdx.x & 31;
    int h    = (blockIdx.x >> 5) & 3;
    int jh   = blockIdx.x >> 7;
    int i0   = tile * 128;
    int jb   = jh * JHALF;

    int q4 = lane & 3;
    int rg = lane >> 2;
    int rbase = wid * 32 + rg;       // warp owns rows rbase + {0,8,16,24}

    float E1[4], E2[4];
#pragma unroll
    for (int rr = 0; rr < 4; rr++) {
        E1[rr] = __ldg(&g_e1i[h * Lq + i0 + rbase + rr * 8]);
        E2[rr] = __ldg(&g_e2i[h * Lq + i0 + rbase + rr * 8]);
    }

#define PREF_B(c, nb) do {                                                     \
        _Pragma("unroll")                                                      \
        for (int q = 0; q < 4; q++) {                                          \
            int idx = tid + q * 128;                                           \
            int n = idx >> 3, k4 = idx & 7;                                    \
            cpa16(smb + SM_B + (nb) * BBUF * 4 + n * (BPAD * 4) + k4 * 16,     \
                  &g_WhT[(size_t)(h * HD + n) * Lq + jb + (c) * CJ + k4 * 4]); \
        }                                                                      \
        CPA_COMMIT();                                                          \
    } while (0)

    PREF_B(0, 0);
#pragma unroll
    for (int q = 0; q < 16; q++) {
        int idx = tid + q * 128;
        int w = idx >> 5, r4 = idx & 31;
        cpa16(smb + SM_MASK + idx * 16,
              &g_maskT[(size_t)(jh * JC + w) * Lq + i0 + r4 * 4]);
    }
#pragma unroll
    for (int q = 0; q < 8; q++) {
        int idx = tid + q * 128;
        cpa16(smb + SM_EJP + idx * 16,
              &g_ejp[(size_t)(h * (Lq / 8) + jb / 8) * 16 + idx * 4]);
    }
    CPA_COMMIT();
    CPA_WAIT0();
    __syncthreads();

    float c_acc[2][8][4];
#pragma unroll
    for (int tt = 0; tt < 2; tt++)
#pragma unroll
        for (int t = 0; t < 8; t++)
#pragma unroll
            for (int p = 0; p < 4; p++) c_acc[tt][t][p] = 0.f;
    float dsum[4] = {0.f, 0.f, 0.f, 0.f};

    for (int c = 0; c < JC; c++) {
        int cur = c & 1;
        if (c + 1 < JC) PREF_B(c + 1, cur ^ 1);

        uint32_t mw[4];
#pragma unroll
        for (int rr = 0; rr < 4; rr++)
            mw[rr] = mask_s[c * 128 + rbase + rr * 8] >> q4;
        const float* bb = b_s + cur * BBUF + rg * BPAD;

#pragma unroll
        for (int ks = 0; ks < 4; ks++) {
            float4 ee = ejp_s[(c * 4 + ks) * 4 + q4];   // e1a,e2a,e1b,e2b
            float ma[4], mb[4];
#pragma unroll
            for (int rr = 0; rr < 4; rr++) {
                float v1 = fmaxf(E1[rr] * ee.x, E2[rr] * ee.y);
                float v2 = fmaxf(E1[rr] * ee.z, E2[rr] * ee.w);
                ma[rr] = (mw[rr] & (1u << (ks * 8)))     ? v1 : 0.f;
                mb[rr] = (mw[rr] & (1u << (ks * 8 + 4))) ? v2 : 0.f;
                dsum[rr] += ma[rr] + mb[rr];
            }
            uint32_t a00 = __float_as_uint(ma[0]), a01 = __float_as_uint(ma[1]);
            uint32_t a02 = __float_as_uint(mb[0]), a03 = __float_as_uint(mb[1]);
            uint32_t a10 = __float_as_uint(ma[2]), a11 = __float_as_uint(ma[3]);
            uint32_t a12 = __float_as_uint(mb[2]), a13 = __float_as_uint(mb[3]);
#pragma unroll
            for (int t = 0; t < 8; t++) {
                uint2 b01 = *(const uint2*)&bb[t * 8 * BPAD + ks * 8 + q4 * 2];
                mma_tf32(c_acc[0][t], a00, a01, a02, a03, b01.x, b01.y);
                mma_tf32(c_acc[1][t], a10, a11, a12, a13, b01.x, b01.y);
            }
        }

        if (c + 1 < JC) CPA_WAIT0();
        __syncthreads();
    }

    // denominators: reduce over the 4 lanes sharing a row
#pragma unroll
    for (int rr = 0; rr < 4; rr++) {
#pragma unroll
        for (int o = 1; o <= 2; o <<= 1)
            dsum[rr] += __shfl_xor_sync(0xffffffffu, dsum[rr], o);
    }
    if (q4 == 0) {
#pragma unroll
        for (int rr = 0; rr < 4; rr++)
            g_den[(size_t)jh * NH * Lq + h * Lq + i0 + rbase + rr * 8] = dsum[rr];
    }

    // partial writeback
    int col0 = h * HD + q4 * 2;
#pragma unroll
    for (int tt = 0; tt < 2; tt++) {
        int row1 = i0 + rbase + tt * 16;
        int row2 = row1 + 8;
        float* d1 = g_patt + (size_t)jh * Lq * DOUTC + (size_t)row1 * DOUTC + col0;
        float* d2 = g_patt + (size_t)jh * Lq * DOUTC + (size_t)row2 * DOUTC + col0;
#pragma unroll
        for (int t = 0; t < 8; t++) {
            *(float2*)(d1 + t * 8) = make_float2(c_acc[tt][t][0], c_acc[tt][t][1]);
            *(float2*)(d2 + t * 8) = make_float2(c_acc[tt][t][2], c_acc[tt][t][3]);
        }
    }
}

// ---------------- launch ------------------------------------------------------
extern "C" void kernel_launch(void* const* d_in, const int* in_sizes, int n_in,
                              void* d_out, int out_size) {
    const float* h     = (const float*)d_in[0];
    const int*   A     = (const int*)d_in[1];
    const float* W     = (const float*)d_in[2];
    const float* attn  = (const float*)d_in[3];
    const float* out_w = (const float*)d_in[4];
    const float* out_b = (const float*)d_in[5];
    float*       out   = (float*)d_out;

    // gemm0 with fused s-tables (attn vector passed through the bias slot)
    gemm64_nt<DIN, 0><<<dim3(DOUTC / 64, Lq / 64), 256>>>(h, W, nullptr, attn);
    mask_kernel<<<Lq / 8, 256>>>(A);
    cudaFuncSetAttribute(gat_attn_mma,
                         cudaFuncAttributeMaxDynamicSharedMemorySize, SM_TOT);
    gat_attn_mma<<<(Lq / 128) * NH * 2, 128, SM_TOT>>>();
    dinv_kernel<<<(NH * Lq) / 256, 256>>>();
    gemm64_nt<DOUTC, 1><<<dim3(DOUTC / 64, Lq / 64), 256>>>(nullptr, out_w, out, out_b);
}